// round 10
// baseline (speedup 1.0000x reference)
#include <cuda_runtime.h>

// SPU transformer bounds propagation — elementwise over (N,2) float32 pairs.
// spu(x) = x>=0 ? x*x - 0.5 : sigmoid(-x) - 1
// For x<0:  sigmoid(-x) - 1 = -0.5*tanh(x/2) - 0.5   (one MUFU.TANH)
//
// Selection (per row, l <= u):
//   neg  (u<=0):  lower=vl,   upper=vu
//   pos  (l>=0):  lower=0,    upper=0
//   cross:        lower = (vu>=vl) ? -0.5 : 0     (sign(slope)==sign(vu-vl), u-l>0)
//                 upper = max(vl, vu)             (cpos->vu, cneg->vl — both the max)
//
// Roofline status: kernel sits at the B300 path-independent LTS streaming cap
// (~6300 B/cyc ~= 7.3 TB/s @NAT): 134 MB L1<->L2 / 7.3 TB/s ~= 18.3 us floor,
// confirmed across MLP / vector width / cache policy / grid / occupancy.
// Final untested cell: MLP=4 at 256-bit width (4 front-batched LDG.256 per
// thread, 128 B in flight) — deeper per-thread MLP for LTS saturation during
// ramp. Everything else identical to the round-9 best (20.99 us).

__device__ __forceinline__ float tanh_approx(float x) {
    float y;
    asm("tanh.approx.f32 %0, %1;" : "=f"(y) : "f"(x));
    return y;
}

__device__ __forceinline__ float spu(float x) {
    float q = fmaf(x, x, -0.5f);
    float t = tanh_approx(0.5f * x);
    float n = fmaf(-0.5f, t, -0.5f);
    return (x >= 0.0f) ? q : n;
}

__device__ __forceinline__ void spu_pair(float l, float u, float& lower, float& upper) {
    float vl = spu(l);
    float vu = spu(u);

    if (u <= 0.0f) {                         // neg: both endpoints <= 0
        lower = vl;
        upper = vu;
    } else if (l >= 0.0f) {                  // pos
        lower = 0.0f;
        upper = 0.0f;
    } else {                                 // cross: l < 0 < u, so u-l > 0 strictly
        lower = (vu >= vl) ? -0.5f : 0.0f;
        upper = fmaxf(vl, vu);
    }
}

__device__ __forceinline__ void ldg256(const float* p, float r[8]) {
    asm volatile("ld.global.nc.v8.f32 {%0,%1,%2,%3,%4,%5,%6,%7}, [%8];"
                 : "=f"(r[0]), "=f"(r[1]), "=f"(r[2]), "=f"(r[3]),
                   "=f"(r[4]), "=f"(r[5]), "=f"(r[6]), "=f"(r[7])
                 : "l"(p));
}

__device__ __forceinline__ void stg256_ef(float* p, const float r[8]) {
    asm volatile("st.global.L2::evict_first.v8.f32 [%0], {%1,%2,%3,%4,%5,%6,%7,%8};"
                 :: "l"(p),
                    "f"(r[0]), "f"(r[1]), "f"(r[2]), "f"(r[3]),
                    "f"(r[4]), "f"(r[5]), "f"(r[6]), "f"(r[7])
                 : "memory");
}

__device__ __forceinline__ void spu_oct(const float a[8], float r[8]) {
    spu_pair(a[0], a[1], r[0], r[1]);
    spu_pair(a[2], a[3], r[2], r[3]);
    spu_pair(a[4], a[5], r[4], r[5]);
    spu_pair(a[6], a[7], r[6], r[7]);
}

__global__ void __launch_bounds__(256)
spu_bounds_kernel(const float* __restrict__ in, float* __restrict__ out,
                  int n8, int stride8) {
    int t = blockIdx.x * blockDim.x + threadIdx.x;
    int i0 = t;
    int i1 = t + stride8;
    int i2 = i1 + stride8;
    int i3 = i2 + stride8;

    if (i3 < n8) {
        // Four independent 256-bit loads issued back-to-back (MLP_p1 = 4).
        float a0[8], a1[8], a2[8], a3[8];
        ldg256(in + (size_t)i0 * 8, a0);
        ldg256(in + (size_t)i1 * 8, a1);
        ldg256(in + (size_t)i2 * 8, a2);
        ldg256(in + (size_t)i3 * 8, a3);

        float r0[8], r1[8], r2[8], r3[8];
        spu_oct(a0, r0);
        spu_oct(a1, r1);
        spu_oct(a2, r2);
        spu_oct(a3, r3);

        stg256_ef(out + (size_t)i0 * 8, r0);
        stg256_ef(out + (size_t)i1 * 8, r1);
        stg256_ef(out + (size_t)i2 * 8, r2);
        stg256_ef(out + (size_t)i3 * 8, r3);
    } else {
        // Ragged tail (not taken when n8 divides evenly).
        for (int i = i0; i < n8; i += stride8) {
            float a[8], r[8];
            ldg256(in + (size_t)i * 8, a);
            spu_oct(a, r);
            stg256_ef(out + (size_t)i * 8, r);
        }
    }
}

extern "C" void kernel_launch(void* const* d_in, const int* in_sizes, int n_in,
                              void* d_out, int out_size) {
    const float* in = (const float*)d_in[0];
    float* out = (float*)d_out;

    int total_floats = in_sizes[0];     // N*2 = 16,777,216
    int n8 = total_floats / 8;          // 2,097,152 32-byte groups

    const int threads = 256;
    const int per_thread = 4;           // four 256-bit groups per thread
    int blocks = (n8 + threads * per_thread - 1) / (threads * per_thread);  // 2048
    int stride8 = blocks * threads;     // 524,288

    spu_bounds_kernel<<<blocks, threads>>>(in, out, n8, stride8);
}

// round 11
// speedup vs baseline: 1.0122x; 1.0122x over previous
#include <cuda_runtime.h>

// SPU transformer bounds propagation — elementwise over (N,2) float32 pairs.
// spu(x) = x>=0 ? x*x - 0.5 : sigmoid(-x) - 1
// For x<0:  sigmoid(-x) - 1 = -0.5*tanh(x/2) - 0.5   (one MUFU.TANH)
//
// Selection (per row, l <= u):
//   neg  (u<=0):  lower=vl,   upper=vu
//   pos  (l>=0):  lower=0,    upper=0
//   cross:        lower = (vu>=vl) ? -0.5 : 0     (sign(slope)==sign(vu-vl), u-l>0)
//                 upper = max(vl, vu)             (cpos->vu, cneg->vl — both the max)
//
// FINAL configuration (session best: kernel 18.43us, harness 20.99us).
// Roofline claimed: the kernel sits at the B300 path-independent LTS
// streaming cap (~6300 B/cyc ~= 7.3 TB/s @NAT). 134 MB of L1<->L2 traffic
// / 7.3 TB/s ~= 18.3 us — the measured floor across the full experiment
// matrix (MLP 2/4, vec 128/256-bit, 7 cache policies, 3 grid shapes,
// occupancy 47-86%). MLP=4 @256-bit regressed via register pressure
// (48 regs -> occ 47%); this MLP=2 shape at 33 regs is the optimum.
//   - 256-bit .nc loads (lowest measured kernel time)
//   - evict_first stores (write-once stream; preserves input L2 residency
//     across graph replays; best measured harness time)
//   - 4096 blocks x 256 threads, one-shot, MLP = 2 x 256-bit per thread
//   - minimal selection tree (compare replaces slope division; max replaces
//     the cross-case nested select); MUFU.TANH negative branch

__device__ __forceinline__ float tanh_approx(float x) {
    float y;
    asm("tanh.approx.f32 %0, %1;" : "=f"(y) : "f"(x));
    return y;
}

__device__ __forceinline__ float spu(float x) {
    float q = fmaf(x, x, -0.5f);
    float t = tanh_approx(0.5f * x);
    float n = fmaf(-0.5f, t, -0.5f);
    return (x >= 0.0f) ? q : n;
}

__device__ __forceinline__ void spu_pair(float l, float u, float& lower, float& upper) {
    float vl = spu(l);
    float vu = spu(u);

    if (u <= 0.0f) {                         // neg: both endpoints <= 0
        lower = vl;
        upper = vu;
    } else if (l >= 0.0f) {                  // pos
        lower = 0.0f;
        upper = 0.0f;
    } else {                                 // cross: l < 0 < u, so u-l > 0 strictly
        lower = (vu >= vl) ? -0.5f : 0.0f;
        upper = fmaxf(vl, vu);
    }
}

__device__ __forceinline__ void ldg256(const float* p, float r[8]) {
    asm volatile("ld.global.nc.v8.f32 {%0,%1,%2,%3,%4,%5,%6,%7}, [%8];"
                 : "=f"(r[0]), "=f"(r[1]), "=f"(r[2]), "=f"(r[3]),
                   "=f"(r[4]), "=f"(r[5]), "=f"(r[6]), "=f"(r[7])
                 : "l"(p));
}

__device__ __forceinline__ void stg256_ef(float* p, const float r[8]) {
    asm volatile("st.global.L2::evict_first.v8.f32 [%0], {%1,%2,%3,%4,%5,%6,%7,%8};"
                 :: "l"(p),
                    "f"(r[0]), "f"(r[1]), "f"(r[2]), "f"(r[3]),
                    "f"(r[4]), "f"(r[5]), "f"(r[6]), "f"(r[7])
                 : "memory");
}

__device__ __forceinline__ void spu_oct(const float a[8], float r[8]) {
    spu_pair(a[0], a[1], r[0], r[1]);
    spu_pair(a[2], a[3], r[2], r[3]);
    spu_pair(a[4], a[5], r[4], r[5]);
    spu_pair(a[6], a[7], r[6], r[7]);
}

__global__ void __launch_bounds__(256)
spu_bounds_kernel(const float* __restrict__ in, float* __restrict__ out,
                  int n8, int stride8) {
    int t = blockIdx.x * blockDim.x + threadIdx.x;
    int i0 = t;
    int i1 = t + stride8;

    if (i1 < n8) {
        // Two independent 256-bit loads issued back-to-back (MLP=2).
        float a0[8], a1[8];
        ldg256(in + (size_t)i0 * 8, a0);
        ldg256(in + (size_t)i1 * 8, a1);

        float r0[8], r1[8];
        spu_oct(a0, r0);
        spu_oct(a1, r1);

        stg256_ef(out + (size_t)i0 * 8, r0);
        stg256_ef(out + (size_t)i1 * 8, r1);
    } else if (i0 < n8) {
        float a0[8], r0[8];
        ldg256(in + (size_t)i0 * 8, a0);
        spu_oct(a0, r0);
        stg256_ef(out + (size_t)i0 * 8, r0);
    }
}

extern "C" void kernel_launch(void* const* d_in, const int* in_sizes, int n_in,
                              void* d_out, int out_size) {
    const float* in = (const float*)d_in[0];
    float* out = (float*)d_out;

    int total_floats = in_sizes[0];     // N*2 = 16,777,216
    int n8 = total_floats / 8;          // 2,097,152 32-byte groups

    const int threads = 256;
    const int per_thread = 2;           // two 256-bit groups per thread
    int blocks = (n8 + threads * per_thread - 1) / (threads * per_thread);  // 4096
    int stride8 = blocks * threads;     // 1,048,576

    spu_bounds_kernel<<<blocks, threads>>>(in, out, n8, stride8);
}

// round 12
// speedup vs baseline: 1.0137x; 1.0015x over previous
#include <cuda_runtime.h>

// SPU transformer bounds propagation — elementwise over (N,2) float32 pairs.
// spu(x) = x>=0 ? x*x - 0.5 : sigmoid(-x) - 1
// For x<0:  sigmoid(-x) - 1 = -0.5*tanh(x/2) - 0.5   (one MUFU.TANH)
//
// Selection (per row, l <= u):
//   neg  (u<=0):  lower=vl,   upper=vu
//   pos  (l>=0):  lower=0,    upper=0
//   cross:        lower = (vu>=vl) ? -0.5 : 0     (sign(slope)==sign(vu-vl), u-l>0)
//                 upper = max(vl, vu)             (cpos->vu, cneg->vl — both the max)
//
// Configuration = session-best round-9 body (kernel 18.2us, harness 20.99us,
// at the B300 path-independent LTS streaming cap: 134 MB L1<->L2 / ~7.3 TB/s).
// Only change this round: block size 256 -> 512 (blocks 4096 -> 2048), the
// one launch parameter never varied. Fuller trailing wave (84% vs 46%
// populated) and half the CTA launch count; body byte-identical.
//   - 256-bit .nc loads, evict_first 256-bit stores
//   - MLP = 2 x 256-bit per thread, 33 regs
//   - minimal selection tree, MUFU.TANH negative branch

__device__ __forceinline__ float tanh_approx(float x) {
    float y;
    asm("tanh.approx.f32 %0, %1;" : "=f"(y) : "f"(x));
    return y;
}

__device__ __forceinline__ float spu(float x) {
    float q = fmaf(x, x, -0.5f);
    float t = tanh_approx(0.5f * x);
    float n = fmaf(-0.5f, t, -0.5f);
    return (x >= 0.0f) ? q : n;
}

__device__ __forceinline__ void spu_pair(float l, float u, float& lower, float& upper) {
    float vl = spu(l);
    float vu = spu(u);

    if (u <= 0.0f) {                         // neg: both endpoints <= 0
        lower = vl;
        upper = vu;
    } else if (l >= 0.0f) {                  // pos
        lower = 0.0f;
        upper = 0.0f;
    } else {                                 // cross: l < 0 < u, so u-l > 0 strictly
        lower = (vu >= vl) ? -0.5f : 0.0f;
        upper = fmaxf(vl, vu);
    }
}

__device__ __forceinline__ void ldg256(const float* p, float r[8]) {
    asm volatile("ld.global.nc.v8.f32 {%0,%1,%2,%3,%4,%5,%6,%7}, [%8];"
                 : "=f"(r[0]), "=f"(r[1]), "=f"(r[2]), "=f"(r[3]),
                   "=f"(r[4]), "=f"(r[5]), "=f"(r[6]), "=f"(r[7])
                 : "l"(p));
}

__device__ __forceinline__ void stg256_ef(float* p, const float r[8]) {
    asm volatile("st.global.L2::evict_first.v8.f32 [%0], {%1,%2,%3,%4,%5,%6,%7,%8};"
                 :: "l"(p),
                    "f"(r[0]), "f"(r[1]), "f"(r[2]), "f"(r[3]),
                    "f"(r[4]), "f"(r[5]), "f"(r[6]), "f"(r[7])
                 : "memory");
}

__device__ __forceinline__ void spu_oct(const float a[8], float r[8]) {
    spu_pair(a[0], a[1], r[0], r[1]);
    spu_pair(a[2], a[3], r[2], r[3]);
    spu_pair(a[4], a[5], r[4], r[5]);
    spu_pair(a[6], a[7], r[6], r[7]);
}

__global__ void __launch_bounds__(512)
spu_bounds_kernel(const float* __restrict__ in, float* __restrict__ out,
                  int n8, int stride8) {
    int t = blockIdx.x * blockDim.x + threadIdx.x;
    int i0 = t;
    int i1 = t + stride8;

    if (i1 < n8) {
        // Two independent 256-bit loads issued back-to-back (MLP=2).
        float a0[8], a1[8];
        ldg256(in + (size_t)i0 * 8, a0);
        ldg256(in + (size_t)i1 * 8, a1);

        float r0[8], r1[8];
        spu_oct(a0, r0);
        spu_oct(a1, r1);

        stg256_ef(out + (size_t)i0 * 8, r0);
        stg256_ef(out + (size_t)i1 * 8, r1);
    } else if (i0 < n8) {
        float a0[8], r0[8];
        ldg256(in + (size_t)i0 * 8, a0);
        spu_oct(a0, r0);
        stg256_ef(out + (size_t)i0 * 8, r0);
    }
}

extern "C" void kernel_launch(void* const* d_in, const int* in_sizes, int n_in,
                              void* d_out, int out_size) {
    const float* in = (const float*)d_in[0];
    float* out = (float*)d_out;

    int total_floats = in_sizes[0];     // N*2 = 16,777,216
    int n8 = total_floats / 8;          // 2,097,152 32-byte groups

    const int threads = 512;
    const int per_thread = 2;           // two 256-bit groups per thread
    int blocks = (n8 + threads * per_thread - 1) / (threads * per_thread);  // 2048
    int stride8 = blocks * threads;     // 1,048,576

    spu_bounds_kernel<<<blocks, threads>>>(in, out, n8, stride8);
}